// round 14
// baseline (speedup 1.0000x reference)
#include <cuda_runtime.h>
#include <cuda_bf16.h>
#include <math.h>
#include <stdint.h>

#define N_TOK 131072
#define BATCH 64
#define H 512

// Scratch (no cudaMalloc allowed)
__device__ float g_P[BATCH * H];
__device__ float g_scores[N_TOK];
__device__ __nv_bfloat16 g_W2hi[H * H];
__device__ __nv_bfloat16 g_W2lo[H * H];

// ---------------- helpers ----------------
static __device__ __forceinline__ uint32_t cvta_s(const void* p) {
  return (uint32_t)__cvta_generic_to_shared(p);
}
static __device__ __forceinline__ void ldsm4(uint32_t& r0, uint32_t& r1,
                                             uint32_t& r2, uint32_t& r3,
                                             uint32_t a) {
  asm volatile("ldmatrix.sync.aligned.m8n8.x4.shared.b16 {%0,%1,%2,%3}, [%4];"
               : "=r"(r0), "=r"(r1), "=r"(r2), "=r"(r3)
               : "r"(a));
}
static __device__ __forceinline__ void mma16816(float* c, const uint32_t* a,
                                                uint32_t b0, uint32_t b1) {
  asm volatile(
      "mma.sync.aligned.m16n8k16.row.col.f32.bf16.bf16.f32 "
      "{%0,%1,%2,%3}, {%4,%5,%6,%7}, {%8,%9}, {%0,%1,%2,%3};"
      : "+f"(c[0]), "+f"(c[1]), "+f"(c[2]), "+f"(c[3])
      : "r"(a[0]), "r"(a[1]), "r"(a[2]), "r"(a[3]), "r"(b0), "r"(b1));
}
static __device__ __forceinline__ void cp16(uint32_t dst, const void* src) {
  asm volatile("cp.async.cg.shared.global [%0], [%1], 16;" ::
               "r"(dst), "l"(src));
}
#define CP_COMMIT() asm volatile("cp.async.commit_group;" ::: "memory")
#define CP_WAIT(n) asm volatile("cp.async.wait_group %0;" :: "n"(n) : "memory")

static __device__ __forceinline__ uint32_t pack_bf2(float a, float b) {
  return (uint32_t)__bfloat16_as_ushort(__float2bfloat16_rn(a)) |
         ((uint32_t)__bfloat16_as_ushort(__float2bfloat16_rn(b)) << 16);
}
static __device__ __forceinline__ float bf_res(float x) {
  return x - __bfloat162float(__float2bfloat16_rn(x));
}
// split pair (a,b) into packed bf16 hi and lo words
static __device__ __forceinline__ void split2(float a, float b, uint32_t& hi,
                                              uint32_t& lo) {
  uint32_t w = pack_bf2(a, b);
  float ha = __uint_as_float(w << 16);
  float hb = __uint_as_float(w & 0xffff0000u);
  hi = w;
  lo = pack_bf2(a - ha, b - hb);
}
// tanh(x) = 1 - 2/(e^{2x}+1) (algebraically exact)
static __device__ __forceinline__ float ftanh(float x) {
  float e = __expf(2.0f * x);
  return 1.0f - __fdividef(2.0f, e + 1.0f);
}

// ---------------- Kernel 0: split W2 (cols 512..1023 of W) into bf16 hi/lo --
__global__ void k_convert_W2(const float* __restrict__ W) {
  int i = blockIdx.x * blockDim.x + threadIdx.x;
  int h = i >> 9, k = i & 511;
  float x = W[h * 1024 + 512 + k];
  __nv_bfloat16 hi = __float2bfloat16_rn(x);
  g_W2hi[i] = hi;
  g_W2lo[i] = __float2bfloat16_rn(x - __bfloat162float(hi));
}

// ---------------- Kernel 1: P[b,h] = sum_k hidden[b,k] * W[h,k] ------------
__global__ void k_precompute_P(const float* __restrict__ hidden,
                               const float* __restrict__ W) {
  int b = blockIdx.x, hy = blockIdx.y;
  int tid = threadIdx.x;
  int hloc = tid >> 2, part = tid & 3;
  int h = hy * 64 + hloc;
  __shared__ float hs[H];
  __shared__ float red[64][4];
  hs[tid] = hidden[b * H + tid];
  hs[tid + 256] = hidden[b * H + tid + 256];
  __syncthreads();
  const float4* wr =
      reinterpret_cast<const float4*>(W + (size_t)h * (2 * H) + part * 128);
  const float* hh = &hs[part * 128];
  float acc = 0.f;
#pragma unroll 8
  for (int k4 = 0; k4 < 32; k4++) {
    float4 w = wr[k4];
    acc += w.x * hh[k4 * 4] + w.y * hh[k4 * 4 + 1] + w.z * hh[k4 * 4 + 2] +
           w.w * hh[k4 * 4 + 3];
  }
  red[hloc][part] = acc;
  __syncthreads();
  if (tid < 64)
    g_P[b * H + hy * 64 + tid] =
        red[tid][0] + red[tid][1] + red[tid][2] + red[tid][3];
}

// ---------------- Kernel 2: fused split-bf16 MMA GEMM + tanh + v-dot --------
// 128x128x32 tiles; flat 64-chunk loop (4 n-passes x 16 k-chunks);
// ring-3 cp.async pipeline (stage = A fp32 16KB + Bhi 8KB + Blo 8KB);
// in-kernel pair-local A fp32 -> bf16 hi/lo conversion, named-barrier synced.
#define OPSZ 8192            // 128 rows * 64B (one bf16 operand-half)
#define STG 32768            // stage = Afp32(16K), Bhi(8K), Blo(8K)
#define BHI_OFF 16384
#define BLO_OFF 24576
#define ABF_HI 98304         // 3 * STG
#define ABF_LO 106496
#define RED_OFF 114688
#define SMEM_FUSED (RED_OFF + 1024)  // 115712

__global__ __launch_bounds__(256, 2) void k_fused_mma(
    const float* __restrict__ enc, const int* __restrict__ seg,
    const float* __restrict__ v) {
  extern __shared__ char sm[];
  const int tid = threadIdx.x;
  const int wid = tid >> 5, lid = tid & 31;
  const int wm = wid & 3, wn = wid >> 2;  // 4 x 2 warp grid
  const int m0 = blockIdx.x * 128;
  const int gID = lid >> 2, tig = lid & 3;
  const uint32_t sbase = cvta_s(sm);

  // ---- per-lane ldmatrix constants (XOR swizzle), A buffers are fixed ----
  const int x15 = lid & 15;
  const int hi16 = lid >> 4;
  const int lswz = (x15 >> 1) & 3;
  const uint32_t akh0 = (uint32_t)((hi16 ^ lswz) * 16);        // k-half 0 atom
  const uint32_t akh1 = (uint32_t)(((2 + hi16) ^ lswz) * 16);  // k-half 1 atom
  const uint32_t arow = (uint32_t)((wm * 32 + x15) * 64);
  const uint32_t brow = (uint32_t)((wn * 64 + x15) * 64);
  const uint32_t abh_base = sbase + ABF_HI + arow;
  const uint32_t abl_base = sbase + ABF_LO + arow;

  // ---- cp.async staging constants ----
  // B (bf16): rows tid>>2 and tid>>2+64, atom tid&3 (64B rows, xor swizzle)
  const int srow0 = tid >> 2, sc = tid & 3;
  const uint32_t sto0 =
      (uint32_t)(srow0 * 64 + ((sc ^ ((srow0 >> 1) & 3)) * 16));
  const uint32_t sto1 = sto0 + 4096;  // row + 64 (same swizzle phase)
  const __nv_bfloat16* pBhi0 = g_W2hi + (size_t)srow0 * H + sc * 8;
  const __nv_bfloat16* pBlo0 = g_W2lo + (size_t)srow0 * H + sc * 8;
  const __nv_bfloat16* pBhi1 = pBhi0 + (size_t)64 * H;
  const __nv_bfloat16* pBlo1 = pBlo0 + (size_t)64 * H;
  // A (fp32): row tid>>1 (128B rows of 8 atoms), group tid&1 -> atoms g*4..+3,
  // physical atom = a ^ (row&7)
  const int ra = tid >> 1, ga = tid & 1;
  const float* pA = enc + (size_t)(m0 + ra) * H + ga * 16;
  uint32_t adst[4];
#pragma unroll
  for (int i = 0; i < 4; i++)
    adst[i] = (uint32_t)(ra * 128 + (((ga * 4 + i) ^ (ra & 7)) * 16));

#define ISSUE_STAGE(cc, ibf)                                         \
  do {                                                               \
    const uint32_t db = sbase + (uint32_t)(ibf)*STG;                 \
    const float* srcA = pA + ((cc)&15) * 32;                         \
    cp16(db + adst[0], srcA + 0);                                    \
    cp16(db + adst[1], srcA + 4);                                    \
    cp16(db + adst[2], srcA + 8);                                    \
    cp16(db + adst[3], srcA + 12);                                   \
    const uint32_t eB =                                              \
        (uint32_t)((cc)&15) * 32u + (uint32_t)((cc) >> 4) * 65536u;  \
    cp16(db + BHI_OFF + sto0, pBhi0 + eB);                           \
    cp16(db + BLO_OFF + sto0, pBlo0 + eB);                           \
    cp16(db + BHI_OFF + sto1, pBhi1 + eB);                           \
    cp16(db + BLO_OFF + sto1, pBlo1 + eB);                           \
    CP_COMMIT();                                                     \
  } while (0)

  // ---- conversion constants: pair (wm, wn) converts A rows wm*32+wn*16.. ----
  const int crow = wm * 32 + wn * 16 + (lid >> 1);  // fp32/bf16 row
  const int ch = lid & 1;                           // k-half (16 cols)
  const uint32_t cswz = (uint32_t)((crow >> 1) & 3);
  const uint32_t chid0 = ((uint32_t)(2 * ch) ^ cswz) * 16;
  const uint32_t chid1 = ((uint32_t)(2 * ch + 1) ^ cswz) * 16;
  char* const hidst = sm + ABF_HI + crow * 64;
  char* const lodst = sm + ABF_LO + crow * 64;
  uint32_t csrc[4];
#pragma unroll
  for (int i = 0; i < 4; i++)
    csrc[i] = (uint32_t)(crow * 128 + (((ch * 4 + i) ^ (crow & 7)) * 16));

  // epilogue row metadata
  const float* Pb[2][2];
#pragma unroll
  for (int t = 0; t < 2; t++) {
    int r0 = m0 + wm * 32 + t * 16 + gID;
    Pb[t][0] = g_P + (size_t)seg[r0] * H;
    Pb[t][1] = g_P + (size_t)seg[r0 + 8] * H;
  }

  float rsum[2][2] = {{0.f, 0.f}, {0.f, 0.f}};
  float acc[16][4];
#pragma unroll
  for (int i = 0; i < 16; i++)
#pragma unroll
    for (int q = 0; q < 4; q++) acc[i][q] = 0.f;

  // prologue: stages 0,1 into bufs 0,1
  ISSUE_STAGE(0, 0);
  ISSUE_STAGE(1, 1);

  int cb = 0;  // compute buffer = c % 3
  int ib = 2;  // issue buffer = (c+2) % 3

  for (int c = 0; c < 64; c++) {
    if (c < 63) { CP_WAIT(1); } else { CP_WAIT(0); }
    __syncthreads();  // stage c resident; all reads of buf (c+2)%3 done
    if (c < 62) {
      ISSUE_STAGE(c + 2, ib);
      ib = (ib == 2) ? 0 : ib + 1;
    }

    const uint32_t bb = sbase + (uint32_t)cb * STG;
    const char* bgen = sm + (size_t)cb * STG;
    cb = (cb == 2) ? 0 : cb + 1;

    // ---- convert my pair's 16 A rows: fp32 stage -> bf16 hi/lo buffers ----
    {
      float4 f[4];
#pragma unroll
      for (int i = 0; i < 4; i++)
        f[i] = *reinterpret_cast<const float4*>(bgen + csrc[i]);
      uint32_t h8[8], l8[8];
      split2(f[0].x, f[0].y, h8[0], l8[0]);
      split2(f[0].z, f[0].w, h8[1], l8[1]);
      split2(f[1].x, f[1].y, h8[2], l8[2]);
      split2(f[1].z, f[1].w, h8[3], l8[3]);
      split2(f[2].x, f[2].y, h8[4], l8[4]);
      split2(f[2].z, f[2].w, h8[5], l8[5]);
      split2(f[3].x, f[3].y, h8[6], l8[6]);
      split2(f[3].z, f[3].w, h8[7], l8[7]);
      *reinterpret_cast<uint4*>(hidst + chid0) =
          make_uint4(h8[0], h8[1], h8[2], h8[3]);
      *reinterpret_cast<uint4*>(hidst + chid1) =
          make_uint4(h8[4], h8[5], h8[6], h8[7]);
      *reinterpret_cast<uint4*>(lodst + chid0) =
          make_uint4(l8[0], l8[1], l8[2], l8[3]);
      *reinterpret_cast<uint4*>(lodst + chid1) =
          make_uint4(l8[4], l8[5], l8[6], l8[7]);
    }
    // pair-scoped visibility: both warps of pair wm see converted rows
    asm volatile("bar.sync %0, 64;" :: "r"(wm + 1) : "memory");

    const uint32_t bbh = bb + BHI_OFF + brow;
    const uint32_t bbl = bb + BLO_OFF + brow;

#pragma unroll
    for (int kh = 0; kh < 2; kh++) {
      const uint32_t ak = kh ? akh1 : akh0;
      uint32_t ah[2][4], al[2][4];
#pragma unroll
      for (int t = 0; t < 2; t++) {
        ldsm4(ah[t][0], ah[t][1], ah[t][2], ah[t][3], abh_base + t * 1024 + ak);
        ldsm4(al[t][0], al[t][1], al[t][2], al[t][3], abl_base + t * 1024 + ak);
      }
#pragma unroll
      for (int j2 = 0; j2 < 4; j2++) {
        uint32_t bh[4], bl[4];
        ldsm4(bh[0], bh[1], bh[2], bh[3], bbh + j2 * 1024 + ak);
        ldsm4(bl[0], bl[1], bl[2], bl[3], bbl + j2 * 1024 + ak);
#pragma unroll
        for (int t = 0; t < 2; t++) {
#pragma unroll
          for (int jj = 0; jj < 2; jj++) {
            float* cacc = acc[t * 8 + j2 * 2 + jj];
            mma16816(cacc, ah[t], bh[jj], bh[2 + jj]);  // hi*hi
            mma16816(cacc, ah[t], bl[jj], bl[2 + jj]);  // hi*lo
            mma16816(cacc, al[t], bh[jj], bh[2 + jj]);  // lo*hi
          }
        }
      }
    }

    // ---- end of an n-pass: epilogue (register-only; overlaps next loads) ----
    if ((c & 15) == 15) {
      const int n0 = (c >> 4) * 128;
#pragma unroll
      for (int t = 0; t < 2; t++) {
#pragma unroll
        for (int j = 0; j < 8; j++) {
          const int col = n0 + wn * 64 + j * 8 + tig * 2;
          const float2 vv = *(const float2*)(v + col);
          const float* cc2 = acc[t * 8 + j];
          const float2 p0 = *(const float2*)(Pb[t][0] + col);
          const float2 p1 = *(const float2*)(Pb[t][1] + col);
          rsum[t][0] += vv.x * ftanh(cc2[0] + p0.x) + vv.y * ftanh(cc2[1] + p0.y);
          rsum[t][1] += vv.x * ftanh(cc2[2] + p1.x) + vv.y * ftanh(cc2[3] + p1.y);
        }
      }
#pragma unroll
      for (int i = 0; i < 16; i++)
#pragma unroll
        for (int q = 0; q < 4; q++) acc[i][q] = 0.f;
    }
  }

  // deterministic reduction: shfl across the 4-lane quad, then smem combine
  float* red = (float*)(sm + RED_OFF);
#pragma unroll
  for (int t = 0; t < 2; t++) {
#pragma unroll
    for (int r = 0; r < 2; r++) {
      float s = rsum[t][r];
      s += __shfl_xor_sync(0xffffffffu, s, 1);
      s += __shfl_xor_sync(0xffffffffu, s, 2);
      if (tig == 0) {
        int row_local = wm * 32 + t * 16 + gID + r * 8;
        red[row_local * 2 + wn] = s;
      }
    }
  }
  __syncthreads();
  if (tid < 128) g_scores[m0 + tid] = red[tid * 2] + red[tid * 2 + 1];
}

// ---------------- Kernel 3: segment softmax (segments sorted) ----------------
__global__ void k_softmax(const int* __restrict__ seg, float* __restrict__ out) {
  int b = blockIdx.x;
  int tid = threadIdx.x;
  __shared__ float sred[256];

  int s, e;
  {
    int lo = 0, hi = N_TOK;
    while (lo < hi) {
      int mid = (lo + hi) >> 1;
      if (seg[mid] < b) lo = mid + 1; else hi = mid;
    }
    s = lo;
    hi = N_TOK;
    while (lo < hi) {
      int mid = (lo + hi) >> 1;
      if (seg[mid] < b + 1) lo = mid + 1; else hi = mid;
    }
    e = lo;
  }

  float m = -3.4e38f;
  for (int i = s + tid; i < e; i += 256) m = fmaxf(m, g_scores[i]);
  sred[tid] = m;
  __syncthreads();
  for (int o = 128; o > 0; o >>= 1) {
    if (tid < o) sred[tid] = fmaxf(sred[tid], sred[tid + o]);
    __syncthreads();
  }
  m = sred[0];
  __syncthreads();

  float sum = 0.f;
  for (int i = s + tid; i < e; i += 256) sum += __expf(g_scores[i] - m);
  sred[tid] = sum;
  __syncthreads();
  for (int o = 128; o > 0; o >>= 1) {
    if (tid < o) sred[tid] += sred[tid + o];
    __syncthreads();
  }
  float inv = 1.0f / sred[0];

  for (int i = s + tid; i < e; i += 256) out[i] = __expf(g_scores[i] - m) * inv;
}

// ---------------- launch ----------------
extern "C" void kernel_launch(void* const* d_in, const int* in_sizes, int n_in,
                              void* d_out, int out_size) {
  const float* hidden = (const float*)d_in[0];   // (64, 512)
  const float* enc    = (const float*)d_in[1];   // (131072, 512)
  const int*   seg    = (const int*)d_in[2];     // (131072,)
  const float* W      = (const float*)d_in[3];   // (512, 1024)
  const float* v      = (const float*)d_in[4];   // (512, 1)
  float* out = (float*)d_out;                    // (131072, 1)

  cudaFuncSetAttribute(k_fused_mma, cudaFuncAttributeMaxDynamicSharedMemorySize,
                       SMEM_FUSED);

  k_convert_W2<<<(H * H) / 256, 256>>>(W);
  dim3 pgrid(BATCH, 8);
  k_precompute_P<<<pgrid, 256>>>(hidden, W);
  k_fused_mma<<<N_TOK / 128, 256, SMEM_FUSED>>>(enc, seg, v);
  k_softmax<<<BATCH, 256>>>(seg, out);
}

// round 17
// speedup vs baseline: 1.0336x; 1.0336x over previous
#include <cuda_runtime.h>
#include <cuda_bf16.h>
#include <math.h>
#include <stdint.h>

#define N_TOK 131072
#define BATCH 64
#define H 512

// Scratch (no cudaMalloc allowed)
__device__ float g_P[BATCH * H];
__device__ float g_scores[N_TOK];
__device__ __nv_bfloat16 g_W2hi[H * H];
__device__ __nv_bfloat16 g_W2lo[H * H];
__device__ __nv_bfloat16 g_Ahi[(size_t)N_TOK * H];  // 134 MB
__device__ __nv_bfloat16 g_Alo[(size_t)N_TOK * H];  // 134 MB

// ---------------- helpers ----------------
static __device__ __forceinline__ uint32_t cvta_s(const void* p) {
  return (uint32_t)__cvta_generic_to_shared(p);
}
static __device__ __forceinline__ void ldsm4(uint32_t& r0, uint32_t& r1,
                                             uint32_t& r2, uint32_t& r3,
                                             uint32_t a) {
  asm volatile("ldmatrix.sync.aligned.m8n8.x4.shared.b16 {%0,%1,%2,%3}, [%4];"
               : "=r"(r0), "=r"(r1), "=r"(r2), "=r"(r3)
               : "r"(a));
}
static __device__ __forceinline__ void mma16816(float* c, const uint32_t* a,
                                                uint32_t b0, uint32_t b1) {
  asm volatile(
      "mma.sync.aligned.m16n8k16.row.col.f32.bf16.bf16.f32 "
      "{%0,%1,%2,%3}, {%4,%5,%6,%7}, {%8,%9}, {%0,%1,%2,%3};"
      : "+f"(c[0]), "+f"(c[1]), "+f"(c[2]), "+f"(c[3])
      : "r"(a[0]), "r"(a[1]), "r"(a[2]), "r"(a[3]), "r"(b0), "r"(b1));
}
static __device__ __forceinline__ void cp16(uint32_t dst, const void* src) {
  asm volatile("cp.async.cg.shared.global [%0], [%1], 16;" ::
               "r"(dst), "l"(src));
}
// .ca variant: also fills L1 — used for B (W2), which the co-resident CTA
// re-reads; its fetch then hits L1 instead of L2.
static __device__ __forceinline__ void cp16ca(uint32_t dst, const void* src) {
  asm volatile("cp.async.ca.shared.global [%0], [%1], 16;" ::
               "r"(dst), "l"(src));
}
#define CP_COMMIT() asm volatile("cp.async.commit_group;" ::: "memory")
#define CP_WAIT(n) asm volatile("cp.async.wait_group %0;" :: "n"(n) : "memory")

static __device__ __forceinline__ uint32_t pack_bf2(float a, float b) {
  return (uint32_t)__bfloat16_as_ushort(__float2bfloat16_rn(a)) |
         ((uint32_t)__bfloat16_as_ushort(__float2bfloat16_rn(b)) << 16);
}
static __device__ __forceinline__ float bf_res(float x) {
  return x - __bfloat162float(__float2bfloat16_rn(x));
}
// tanh(x) = 1 - 2/(e^{2x}+1) (algebraically exact)
static __device__ __forceinline__ float ftanh(float x) {
  float e = __expf(2.0f * x);
  return 1.0f - __fdividef(2.0f, e + 1.0f);
}

// ---------------- Kernel 0a: split W2 (cols 512..1023 of W) into bf16 hi/lo --
__global__ void k_convert_W2(const float* __restrict__ W) {
  int i = blockIdx.x * blockDim.x + threadIdx.x;
  int h = i >> 9, k = i & 511;
  float x = W[h * 1024 + 512 + k];
  __nv_bfloat16 hi = __float2bfloat16_rn(x);
  g_W2hi[i] = hi;
  g_W2lo[i] = __float2bfloat16_rn(x - __bfloat162float(hi));
}

// ---------------- Kernel 0b: split enc into bf16 hi/lo ----------------------
__global__ void k_convert_A(const float* __restrict__ enc) {
  size_t i = ((size_t)blockIdx.x * 256 + threadIdx.x) * 8;
  const float4* src = reinterpret_cast<const float4*>(enc + i);
  float4 u = src[0], w = src[1];
  uint4 hi = make_uint4(pack_bf2(u.x, u.y), pack_bf2(u.z, u.w),
                        pack_bf2(w.x, w.y), pack_bf2(w.z, w.w));
  uint4 lo = make_uint4(
      pack_bf2(bf_res(u.x), bf_res(u.y)), pack_bf2(bf_res(u.z), bf_res(u.w)),
      pack_bf2(bf_res(w.x), bf_res(w.y)), pack_bf2(bf_res(w.z), bf_res(w.w)));
  *reinterpret_cast<uint4*>(g_Ahi + i) = hi;
  *reinterpret_cast<uint4*>(g_Alo + i) = lo;
}

// ---------------- Kernel 1: P[b,h] = sum_k hidden[b,k] * W[h,k] ------------
__global__ void k_precompute_P(const float* __restrict__ hidden,
                               const float* __restrict__ W) {
  int b = blockIdx.x, hy = blockIdx.y;
  int tid = threadIdx.x;
  int hloc = tid >> 2, part = tid & 3;
  int h = hy * 64 + hloc;
  __shared__ float hs[H];
  __shared__ float red[64][4];
  hs[tid] = hidden[b * H + tid];
  hs[tid + 256] = hidden[b * H + tid + 256];
  __syncthreads();
  const float4* wr =
      reinterpret_cast<const float4*>(W + (size_t)h * (2 * H) + part * 128);
  const float* hh = &hs[part * 128];
  float acc = 0.f;
#pragma unroll 8
  for (int k4 = 0; k4 < 32; k4++) {
    float4 w = wr[k4];
    acc += w.x * hh[k4 * 4] + w.y * hh[k4 * 4 + 1] + w.z * hh[k4 * 4 + 2] +
           w.w * hh[k4 * 4 + 3];
  }
  red[hloc][part] = acc;
  __syncthreads();
  if (tid < 64)
    g_P[b * H + hy * 64 + tid] =
        red[tid][0] + red[tid][1] + red[tid][2] + red[tid][3];
}

// ---------------- Kernel 2: fused split-bf16 MMA GEMM + tanh + v-dot --------
// 128x128x32 tiles; flat 64-chunk loop (4 n-passes x 16 k-chunks);
// ring-3 cp.async pipeline, ONE barrier per chunk; XOR-swizzled 64B rows.
#define OPSZ 8192            // 128 rows * 64B per operand-half
#define STG 32768            // stage = Ahi,Alo,Bhi,Blo
#define RED_OFF 98304        // 3 * STG
#define SMEM_FUSED (RED_OFF + 1024)  // 99328

__global__ __launch_bounds__(256, 2) void k_fused_mma(
    const int* __restrict__ seg, const float* __restrict__ v) {
  extern __shared__ char sm[];
  const int tid = threadIdx.x;
  const int wid = tid >> 5, lid = tid & 31;
  const int wm = wid & 3, wn = wid >> 2;  // 4 x 2 warp grid
  const int m0 = blockIdx.x * 128;
  const int gID = lid >> 2, tig = lid & 3;
  const uint32_t sbase = cvta_s(sm);

  // ---- per-lane ldmatrix constants (XOR swizzle) ----
  const int x15 = lid & 15;
  const int hi16 = lid >> 4;
  const int lswz = (x15 >> 1) & 3;
  const uint32_t akh0 = (uint32_t)((hi16 ^ lswz) * 16);        // k-half 0 atom
  const uint32_t akh1 = (uint32_t)(((2 + hi16) ^ lswz) * 16);  // k-half 1 atom
  const uint32_t arow = (uint32_t)((wm * 32 + x15) * 64);
  const uint32_t brow = (uint32_t)((wn * 64 + x15) * 64);

  // ---- cp.async staging constants: rows tid>>2 and tid>>2+64, atom tid&3 ----
  const int srow0 = tid >> 2, sc = tid & 3;
  const uint32_t sto0 =
      (uint32_t)(srow0 * 64 + ((sc ^ ((srow0 >> 1) & 3)) * 16));
  const uint32_t sto1 = sto0 + 4096;  // row + 64 (same swizzle phase)

  const __nv_bfloat16* pAhi0 = g_Ahi + (size_t)(m0 + srow0) * H + sc * 8;
  const __nv_bfloat16* pAlo0 = g_Alo + (size_t)(m0 + srow0) * H + sc * 8;
  const __nv_bfloat16* pAhi1 = pAhi0 + (size_t)64 * H;
  const __nv_bfloat16* pAlo1 = pAlo0 + (size_t)64 * H;
  const __nv_bfloat16* pBhi0 = g_W2hi + (size_t)srow0 * H + sc * 8;
  const __nv_bfloat16* pBlo0 = g_W2lo + (size_t)srow0 * H + sc * 8;
  const __nv_bfloat16* pBhi1 = pBhi0 + (size_t)64 * H;
  const __nv_bfloat16* pBlo1 = pBlo0 + (size_t)64 * H;

#define ISSUE_STAGE(cc, ib)                                          \
  do {                                                               \
    const uint32_t db = sbase + (uint32_t)(ib) * STG;                \
    const uint32_t eA = (uint32_t)((cc) & 15) * 32u;                 \
    const uint32_t eB = eA + (uint32_t)((cc) >> 4) * 65536u;         \
    cp16(db + sto0, pAhi0 + eA);                                     \
    cp16(db + sto0 + OPSZ, pAlo0 + eA);                              \
    cp16ca(db + sto0 + 2 * OPSZ, pBhi0 + eB);                        \
    cp16ca(db + sto0 + 3 * OPSZ, pBlo0 + eB);                        \
    cp16(db + sto1, pAhi1 + eA);                                     \
    cp16(db + sto1 + OPSZ, pAlo1 + eA);                              \
    cp16ca(db + sto1 + 2 * OPSZ, pBhi1 + eB);                        \
    cp16ca(db + sto1 + 3 * OPSZ, pBlo1 + eB);                        \
    CP_COMMIT();                                                     \
  } while (0)

  // epilogue row metadata
  const float* Pb[2][2];
#pragma unroll
  for (int t = 0; t < 2; t++) {
    int r0 = m0 + wm * 32 + t * 16 + gID;
    Pb[t][0] = g_P + (size_t)seg[r0] * H;
    Pb[t][1] = g_P + (size_t)seg[r0 + 8] * H;
  }

  float rsum[2][2] = {{0.f, 0.f}, {0.f, 0.f}};
  float acc[16][4];
#pragma unroll
  for (int i = 0; i < 16; i++)
#pragma unroll
    for (int q = 0; q < 4; q++) acc[i][q] = 0.f;

  // prologue: stages 0,1 into bufs 0,1
  ISSUE_STAGE(0, 0);
  ISSUE_STAGE(1, 1);

  int cb = 0;  // compute buffer = c % 3
  int ib = 2;  // issue buffer = (c+2) % 3

  for (int c = 0; c < 64; c++) {
    if (c < 63) { CP_WAIT(1); } else { CP_WAIT(0); }
    __syncthreads();  // all warps done reading buf (c-1)%3 == write target
    if (c < 62) {
      ISSUE_STAGE(c + 2, ib);
      ib = (ib == 2) ? 0 : ib + 1;
    }

    const uint32_t bb = sbase + (uint32_t)cb * STG;
    cb = (cb == 2) ? 0 : cb + 1;
    const uint32_t abh = bb + arow;
    const uint32_t abl = bb + OPSZ + arow;
    const uint32_t bbh = bb + 2 * OPSZ + brow;
    const uint32_t bbl = bb + 3 * OPSZ + brow;

#pragma unroll
    for (int kh = 0; kh < 2; kh++) {
      const uint32_t ak = kh ? akh1 : akh0;
      uint32_t ah[2][4], al[2][4];
#pragma unroll
      for (int t = 0; t < 2; t++) {
        ldsm4(ah[t][0], ah[t][1], ah[t][2], ah[t][3], abh + t * 1024 + ak);
        ldsm4(al[t][0], al[t][1], al[t][2], al[t][3], abl + t * 1024 + ak);
      }
#pragma unroll
      for (int j2 = 0; j2 < 4; j2++) {
        uint32_t bh[4], bl[4];
        ldsm4(bh[0], bh[1], bh[2], bh[3], bbh + j2 * 1024 + ak);
        ldsm4(bl[0], bl[1], bl[2], bl[3], bbl + j2 * 1024 + ak);
#pragma unroll
        for (int t = 0; t < 2; t++) {
#pragma unroll
          for (int jj = 0; jj < 2; jj++) {
            float* cacc = acc[t * 8 + j2 * 2 + jj];
            mma16816(cacc, ah[t], bh[jj], bh[2 + jj]);  // hi*hi
            mma16816(cacc, ah[t], bl[jj], bl[2 + jj]);  // hi*lo
            mma16816(cacc, al[t], bh[jj], bh[2 + jj]);  // lo*hi
          }
        }
      }
    }

    // ---- end of an n-pass: epilogue (register-only; overlaps next loads) ----
    if ((c & 15) == 15) {
      const int n0 = (c >> 4) * 128;
#pragma unroll
      for (int t = 0; t < 2; t++) {
#pragma unroll
        for (int j = 0; j < 8; j++) {
          const int col = n0 + wn * 64 + j * 8 + tig * 2;
          const float2 vv = *(const float2*)(v + col);
          const float* cc2 = acc[t * 8 + j];
          const float2 p0 = *(const float2*)(Pb[t][0] + col);
          const float2 p1 = *(const float2*)(Pb[t][1] + col);
          rsum[t][0] += vv.x * ftanh(cc2[0] + p0.x) + vv.y * ftanh(cc2[1] + p0.y);
          rsum[t][1] += vv.x * ftanh(cc2[2] + p1.x) + vv.y * ftanh(cc2[3] + p1.y);
        }
      }
#pragma unroll
      for (int i = 0; i < 16; i++)
#pragma unroll
        for (int q = 0; q < 4; q++) acc[i][q] = 0.f;
    }
  }

  // deterministic reduction: shfl across the 4-lane quad, then smem combine
  float* red = (float*)(sm + RED_OFF);
#pragma unroll
  for (int t = 0; t < 2; t++) {
#pragma unroll
    for (int r = 0; r < 2; r++) {
      float s = rsum[t][r];
      s += __shfl_xor_sync(0xffffffffu, s, 1);
      s += __shfl_xor_sync(0xffffffffu, s, 2);
      if (tig == 0) {
        int row_local = wm * 32 + t * 16 + gID + r * 8;
        red[row_local * 2 + wn] = s;
      }
    }
  }
  __syncthreads();
  if (tid < 128) g_scores[m0 + tid] = red[tid * 2] + red[tid * 2 + 1];
}

// ---------------- Kernel 3: segment softmax (online, segments sorted) -------
__global__ void k_softmax(const int* __restrict__ seg, float* __restrict__ out) {
  int b = blockIdx.x;
  int tid = threadIdx.x;
  __shared__ float smax[256];
  __shared__ float ssum[256];

  int s, e;
  {
    int lo = 0, hi = N_TOK;
    while (lo < hi) {
      int mid = (lo + hi) >> 1;
      if (seg[mid] < b) lo = mid + 1; else hi = mid;
    }
    s = lo;
    hi = N_TOK;
    while (lo < hi) {
      int mid = (lo + hi) >> 1;
      if (seg[mid] < b + 1) lo = mid + 1; else hi = mid;
    }
    e = lo;
  }

  // online (max, sum) accumulation — single read pass
  float m = -3.4e38f, sum = 0.f;
  for (int i = s + tid; i < e; i += 256) {
    float x = g_scores[i];
    float mn = fmaxf(m, x);
    sum = sum * __expf(m - mn) + __expf(x - mn);
    m = mn;
  }
  smax[tid] = m;
  ssum[tid] = sum;
  __syncthreads();
  // deterministic pair-merge tree
  for (int o = 128; o > 0; o >>= 1) {
    if (tid < o) {
      float m1 = smax[tid], m2 = smax[tid + o];
      float mn = fmaxf(m1, m2);
      ssum[tid] = ssum[tid] * __expf(m1 - mn) + ssum[tid + o] * __expf(m2 - mn);
      smax[tid] = mn;
    }
    __syncthreads();
  }
  m = smax[0];
  float inv = 1.0f / ssum[0];

  for (int i = s + tid; i < e; i += 256) out[i] = __expf(g_scores[i] - m) * inv;
}

// ---------------- launch ----------------
extern "C" void kernel_launch(void* const* d_in, const int* in_sizes, int n_in,
                              void* d_out, int out_size) {
  const float* hidden = (const float*)d_in[0];   // (64, 512)
  const float* enc    = (const float*)d_in[1];   // (131072, 512)
  const int*   seg    = (const int*)d_in[2];     // (131072,)
  const float* W      = (const float*)d_in[3];   // (512, 1024)
  const float* v      = (const float*)d_in[4];   // (512, 1)
  float* out = (float*)d_out;                    // (131072, 1)

  cudaFuncSetAttribute(k_fused_mma, cudaFuncAttributeMaxDynamicSharedMemorySize,
                       SMEM_FUSED);

  k_convert_W2<<<(H * H) / 256, 256>>>(W);
  k_convert_A<<<(N_TOK * (H / 8)) / 256, 256>>>(enc);
  dim3 pgrid(BATCH, 8);
  k_precompute_P<<<pgrid, 256>>>(hidden, W);
  k_fused_mma<<<N_TOK / 128, 256, SMEM_FUSED>>>(seg, v);
  k_softmax<<<BATCH, 256>>>(seg, out);
}